// round 12
// baseline (speedup 1.0000x reference)
#include <cuda_runtime.h>
#include <math.h>

#define N_NODES 50000
#define N_EDGES 800000
#define D 128
#define HEADS 8
#define UNITS 16

#define GAT_BLOCKS 888           // 148 SMs x 6 resident blocks: persistent grid

// ---------------- device scratch (zero-initialized at load) ----------------
__device__ float g_xp[N_NODES * D];      // 25.6 MB
__device__ int   g_deg[N_NODES];         // degree per target (self-cleaning: gat resets)
__device__ int   g_off[N_NODES];         // start of target's region in g_esrc
__device__ int   g_cur[N_NODES];         // bump cursor for fill
__device__ int   g_esrc[N_EDGES];        // sources grouped by target (compact CSR)
__device__ int   g_total;                // bump allocator (reset by hist_kernel)
__device__ int   g_work;                 // work-stealing cursor (reset by fill_kernel)

__device__ __forceinline__ float lrelu(float v) {
    return fmaxf(v, 0.2f * v);
}

// ---------------- kernel 1: xp = x @ W — wavefront-minimal (R9-exact) ----------------
#define XPAD 20
__global__ void gemm_kernel(const float* __restrict__ x, const float* __restrict__ W) {
    __shared__ float xs_t[D][XPAD];
    int node0 = blockIdx.x * 16;
    int tid = threadIdx.x;
    int cg = tid & 31;
    int ng = tid >> 5;

    #pragma unroll
    for (int m = 0; m < 16; m++)
        xs_t[tid][m] = x[(node0 + m) * D + tid];
    __syncthreads();

    const float4* W4 = (const float4*)W;
    float4 acc0 = make_float4(0.f, 0.f, 0.f, 0.f);
    float4 acc1 = acc0, acc2 = acc0, acc3 = acc0;

    #pragma unroll 8
    for (int k = 0; k < D; k++) {
        float4 w4 = W4[k * 32 + cg];
        float4 xv = *(const float4*)&xs_t[k][4 * ng];
        acc0.x += xv.x * w4.x; acc0.y += xv.x * w4.y; acc0.z += xv.x * w4.z; acc0.w += xv.x * w4.w;
        acc1.x += xv.y * w4.x; acc1.y += xv.y * w4.y; acc1.z += xv.y * w4.z; acc1.w += xv.y * w4.w;
        acc2.x += xv.z * w4.x; acc2.y += xv.z * w4.y; acc2.z += xv.z * w4.z; acc2.w += xv.z * w4.w;
        acc3.x += xv.w * w4.x; acc3.y += xv.w * w4.y; acc3.z += xv.w * w4.z; acc3.w += xv.w * w4.w;
    }

    float4* out4 = (float4*)(g_xp + (size_t)(node0 + 4 * ng) * D);
    out4[0 * 32 + cg] = acc0;
    out4[1 * 32 + cg] = acc1;
    out4[2 * 32 + cg] = acc2;
    out4[3 * 32 + cg] = acc3;
}

// ---------------- kernel 2: degree histogram (R9-exact) ----------------
__global__ void hist_kernel(const int* __restrict__ edges) {
    if (blockIdx.x == 0 && threadIdx.x == 0) g_total = 0;
    int e = blockIdx.x * blockDim.x + threadIdx.x;
    if (e >= N_EDGES) return;
    int tgt = edges[2 * e + 1];
    atomicAdd(&g_deg[tgt], 1);
}

// ---------------- kernel 3: offsets via warp-aggregated bump alloc (R9-exact) ----------------
__global__ void offsets_kernel() {
    int t = blockIdx.x * blockDim.x + threadIdx.x;
    int lane = threadIdx.x & 31;
    int deg = (t < N_NODES) ? g_deg[t] : 0;

    int incl = deg;
    #pragma unroll
    for (int d = 1; d < 32; d <<= 1) {
        int v = __shfl_up_sync(0xffffffffu, incl, d);
        if (lane >= d) incl += v;
    }
    int total = __shfl_sync(0xffffffffu, incl, 31);
    int base = 0;
    if (lane == 31) base = atomicAdd(&g_total, total);
    base = __shfl_sync(0xffffffffu, base, 31);

    if (t < N_NODES) {
        int off = base + incl - deg;
        g_off[t] = off;
        g_cur[t] = off;
    }
}

// ---------------- kernel 4: scatter + reset work cursor (R9-exact + g_work reset) ----------------
__global__ void fill_kernel(const int* __restrict__ edges) {
    if (blockIdx.x == 0 && threadIdx.x == 0) g_work = 0;    // consumed by gat (next launch)
    int e = blockIdx.x * blockDim.x + threadIdx.x;
    if (e >= N_EDGES) return;
    int2 ed = ((const int2*)edges)[e];
    int pos = atomicAdd(&g_cur[ed.y], 1);
    g_esrc[pos] = ed.x;
}

// ---------------- kernel 5: GAT pass — persistent warps, work-stealing ----------------
// Body is R10-exact; only the target acquisition changed (atomic cursor).
__global__ void __launch_bounds__(256, 6)
gat_kernel(const float* __restrict__ ka,
           const float* __restrict__ ba,
           const float* __restrict__ bias,
           float* __restrict__ out) {
    int lane = threadIdx.x & 31;

    float4 k4  = ((const float4*)ka)[lane];
    float4 ba4 = ((const float4*)ba)[lane];
    float4 b4  = ((const float4*)bias)[lane];

    for (;;) {
        int t;
        if (lane == 0) t = atomicAdd(&g_work, 1);
        t = __shfl_sync(0xffffffffu, t, 0);
        if (t >= N_NODES) break;

        int off = g_off[t];
        int deg = g_deg[t];
        if (lane == 0) g_deg[t] = 0;             // self-clean for next replay

        float4 tb = ((const float4*)(g_xp + (size_t)t * D))[lane];
        tb.x += 2.0f * ba4.x; tb.y += 2.0f * ba4.y;
        tb.z += 2.0f * ba4.z; tb.w += 2.0f * ba4.w;

        float4 acc = make_float4(0.0f, 0.0f, 0.0f, 0.0f);
        float wsum = 0.0f;

        if (deg > 0) {
            int last = deg - 1;
            const int* __restrict__ srcs = g_esrc + off;

            float4 a0 = ((const float4*)(g_xp + (size_t)srcs[0] * D))[lane];
            float4 a1 = ((const float4*)(g_xp + (size_t)srcs[min(1, last)] * D))[lane];

            for (int i = 0; i < deg; i++) {
                float4 cur = a0;
                a0 = a1;
                int s = srcs[min(i + 2, last)];
                a1 = ((const float4*)(g_xp + (size_t)s * D))[lane];

                float p = lrelu(cur.x + tb.x) * k4.x
                        + lrelu(cur.y + tb.y) * k4.y
                        + lrelu(cur.z + tb.z) * k4.z
                        + lrelu(cur.w + tb.w) * k4.w;
                p += __shfl_xor_sync(0xffffffffu, p, 1);
                p += __shfl_xor_sync(0xffffffffu, p, 2);

                float w = __expf(p);
                wsum  += w;
                acc.x += w * cur.x; acc.y += w * cur.y;
                acc.z += w * cur.z; acc.w += w * cur.w;
            }
        }

        float inv = 1.0f / (wsum + 1e-7f);
        float v[4] = { acc.x * inv + b4.x, acc.y * inv + b4.y,
                       acc.z * inv + b4.z, acc.w * inv + b4.w };
        #pragma unroll
        for (int j = 0; j < 4; j++) {
            float u = v[j];
            float c = 0.7978845608028654f * (u + 0.044715f * u * u * u);
            v[j] = 0.5f * u * (1.0f + tanhf(c));
        }
        ((float4*)(out + (size_t)t * D))[lane] = make_float4(v[0], v[1], v[2], v[3]);
    }
}

// ---------------- launch: fork gemm onto a side stream, join before gat (R10) ----------------
extern "C" void kernel_launch(void* const* d_in, const int* in_sizes, int n_in,
                              void* d_out, int out_size) {
    const float* x     = (const float*)d_in[0];
    const int*   edges = (const int*)  d_in[1];
    const float* W     = (const float*)d_in[2];
    const float* ka    = (const float*)d_in[3];
    const float* ba    = (const float*)d_in[4];
    const float* bias  = (const float*)d_in[5];
    float* out = (float*)d_out;

    (void)in_sizes; (void)n_in; (void)out_size;

    static cudaStream_t s_side = nullptr;
    static cudaEvent_t  ev_fork = nullptr, ev_join = nullptr;
    if (s_side == nullptr) {
        cudaStreamCreateWithFlags(&s_side, cudaStreamNonBlocking);
        cudaEventCreateWithFlags(&ev_fork, cudaEventDisableTiming);
        cudaEventCreateWithFlags(&ev_join, cudaEventDisableTiming);
    }

    cudaEventRecord(ev_fork, 0);
    cudaStreamWaitEvent(s_side, ev_fork, 0);

    gemm_kernel<<<N_NODES / 16, 128, 0, s_side>>>(x, W);

    hist_kernel<<<(N_EDGES + 255) / 256, 256>>>(edges);
    offsets_kernel<<<(N_NODES + 255) / 256, 256>>>();
    fill_kernel<<<(N_EDGES + 255) / 256, 256>>>(edges);

    cudaEventRecord(ev_join, s_side);
    cudaStreamWaitEvent(0, ev_join, 0);

    gat_kernel<<<GAT_BLOCKS, 256>>>(ka, ba, bias, out);
}

// round 14
// speedup vs baseline: 1.3907x; 1.3907x over previous
#include <cuda_runtime.h>
#include <math.h>

#define N_NODES 50000
#define N_EDGES 800000
#define D 128
#define HEADS 8
#define UNITS 16
#define DBINS 128

// ---------------- device scratch (zero-initialized at load) ----------------
__device__ float g_xp[N_NODES * D];      // 25.6 MB
__device__ int   g_deg[N_NODES];         // degree per target (self-cleaning: gat resets)
__device__ int   g_off[N_NODES];         // start of target's region in g_esrc
__device__ int   g_cur[N_NODES];         // bump cursor for fill
__device__ int   g_esrc[N_EDGES];        // sources grouped by target (compact CSR)
__device__ int   g_total;                // bump allocator (reset by hist_kernel)
__device__ int   g_dbin[DBINS];          // degree histogram bins (zeroed by hist_kernel)
__device__ int   g_dcur[DBINS];          // bin cursors (rewritten by dscan each run)
__device__ int   g_order[N_NODES];       // targets sorted by descending degree

__device__ __forceinline__ float lrelu(float v) {
    return fmaxf(v, 0.2f * v);
}

// ---------------- kernel 1: xp = x @ W — wavefront-minimal (R9-exact) ----------------
#define XPAD 20
__global__ void gemm_kernel(const float* __restrict__ x, const float* __restrict__ W) {
    __shared__ float xs_t[D][XPAD];
    int node0 = blockIdx.x * 16;
    int tid = threadIdx.x;
    int cg = tid & 31;
    int ng = tid >> 5;

    #pragma unroll
    for (int m = 0; m < 16; m++)
        xs_t[tid][m] = x[(node0 + m) * D + tid];
    __syncthreads();

    const float4* W4 = (const float4*)W;
    float4 acc0 = make_float4(0.f, 0.f, 0.f, 0.f);
    float4 acc1 = acc0, acc2 = acc0, acc3 = acc0;

    #pragma unroll 8
    for (int k = 0; k < D; k++) {
        float4 w4 = W4[k * 32 + cg];
        float4 xv = *(const float4*)&xs_t[k][4 * ng];
        acc0.x += xv.x * w4.x; acc0.y += xv.x * w4.y; acc0.z += xv.x * w4.z; acc0.w += xv.x * w4.w;
        acc1.x += xv.y * w4.x; acc1.y += xv.y * w4.y; acc1.z += xv.y * w4.z; acc1.w += xv.y * w4.w;
        acc2.x += xv.z * w4.x; acc2.y += xv.z * w4.y; acc2.z += xv.z * w4.z; acc2.w += xv.z * w4.w;
        acc3.x += xv.w * w4.x; acc3.y += xv.w * w4.y; acc3.z += xv.w * w4.z; acc3.w += xv.w * w4.w;
    }

    float4* out4 = (float4*)(g_xp + (size_t)(node0 + 4 * ng) * D);
    out4[0 * 32 + cg] = acc0;
    out4[1 * 32 + cg] = acc1;
    out4[2 * 32 + cg] = acc2;
    out4[3 * 32 + cg] = acc3;
}

// ---------------- kernel 2: degree histogram (R9-exact + bin zeroing) ----------------
__global__ void hist_kernel(const int* __restrict__ edges) {
    if (blockIdx.x == 0 && threadIdx.x == 0) g_total = 0;
    if (blockIdx.x == 0 && threadIdx.x < DBINS) g_dbin[threadIdx.x] = 0;  // for dhist (next launch)
    int e = blockIdx.x * blockDim.x + threadIdx.x;
    if (e >= N_EDGES) return;
    int tgt = edges[2 * e + 1];
    atomicAdd(&g_deg[tgt], 1);
}

// ---------------- kernel 3: offsets via warp-aggregated bump alloc (R9-exact) ----------------
__global__ void offsets_kernel() {
    int t = blockIdx.x * blockDim.x + threadIdx.x;
    int lane = threadIdx.x & 31;
    int deg = (t < N_NODES) ? g_deg[t] : 0;

    int incl = deg;
    #pragma unroll
    for (int d = 1; d < 32; d <<= 1) {
        int v = __shfl_up_sync(0xffffffffu, incl, d);
        if (lane >= d) incl += v;
    }
    int total = __shfl_sync(0xffffffffu, incl, 31);
    int base = 0;
    if (lane == 31) base = atomicAdd(&g_total, total);
    base = __shfl_sync(0xffffffffu, base, 31);

    if (t < N_NODES) {
        int off = base + incl - deg;
        g_off[t] = off;
        g_cur[t] = off;
    }
}

// ---------------- kernel 4: scatter sources into per-target regions (R9-exact) ----------------
__global__ void fill_kernel(const int* __restrict__ edges) {
    int e = blockIdx.x * blockDim.x + threadIdx.x;
    if (e >= N_EDGES) return;
    int2 ed = ((const int2*)edges)[e];
    int pos = atomicAdd(&g_cur[ed.y], 1);
    g_esrc[pos] = ed.x;
}

// ---------------- degree-sort chain (runs parallel to fill on a side stream) ----------------
// bin = DBINS-1 - min(deg, DBINS-1): descending degree => long tasks first.
__global__ void dhist_kernel() {
    int t = blockIdx.x * blockDim.x + threadIdx.x;
    if (t >= N_NODES) return;
    int bin = (DBINS - 1) - min(g_deg[t], DBINS - 1);
    atomicAdd(&g_dbin[bin], 1);
}

__global__ void dscan_kernel() {           // single block, DBINS=128 threads
    __shared__ int wtot[4];
    int i = threadIdx.x;
    int lane = i & 31, w = i >> 5;
    int v = g_dbin[i];
    int incl = v;
    #pragma unroll
    for (int d = 1; d < 32; d <<= 1) {
        int u = __shfl_up_sync(0xffffffffu, incl, d);
        if (lane >= d) incl += u;
    }
    if (lane == 31) wtot[w] = incl;
    __syncthreads();
    int base = 0;
    #pragma unroll
    for (int j = 0; j < 4; j++) if (j < w) base += wtot[j];
    g_dcur[i] = base + incl - v;           // exclusive prefix
}

__global__ void dorder_kernel() {
    int t = blockIdx.x * blockDim.x + threadIdx.x;
    if (t >= N_NODES) return;
    int bin = (DBINS - 1) - min(g_deg[t], DBINS - 1);
    int pos = atomicAdd(&g_dcur[bin], 1);
    g_order[pos] = t;
}

// ---------------- kernel 5: fused GAT pass, warp per target (R10-exact body) ----------------
// Only change: target picked via degree-sorted g_order -> homogeneous blocks.
__global__ void gat_kernel(const float* __restrict__ ka,
                           const float* __restrict__ ba,
                           const float* __restrict__ bias,
                           float* __restrict__ out) {
    int wid = blockIdx.x * (blockDim.x >> 5) + (threadIdx.x >> 5);
    if (wid >= N_NODES) return;
    int lane = threadIdx.x & 31;

    int t = g_order[wid];

    int off = g_off[t];
    int deg = g_deg[t];
    if (lane == 0) g_deg[t] = 0;                 // self-clean for next replay

    float4 k4  = ((const float4*)ka)[lane];
    float4 ba4 = ((const float4*)ba)[lane];
    float4 tb  = ((const float4*)(g_xp + (size_t)t * D))[lane];
    tb.x += 2.0f * ba4.x; tb.y += 2.0f * ba4.y;
    tb.z += 2.0f * ba4.z; tb.w += 2.0f * ba4.w;

    float4 acc = make_float4(0.0f, 0.0f, 0.0f, 0.0f);
    float wsum = 0.0f;

    if (deg > 0) {
        int last = deg - 1;
        const int* __restrict__ srcs = g_esrc + off;

        float4 a0 = ((const float4*)(g_xp + (size_t)srcs[0] * D))[lane];
        float4 a1 = ((const float4*)(g_xp + (size_t)srcs[min(1, last)] * D))[lane];

        for (int i = 0; i < deg; i++) {
            float4 cur = a0;
            a0 = a1;
            int s = srcs[min(i + 2, last)];
            a1 = ((const float4*)(g_xp + (size_t)s * D))[lane];

            float p = lrelu(cur.x + tb.x) * k4.x
                    + lrelu(cur.y + tb.y) * k4.y
                    + lrelu(cur.z + tb.z) * k4.z
                    + lrelu(cur.w + tb.w) * k4.w;
            p += __shfl_xor_sync(0xffffffffu, p, 1);
            p += __shfl_xor_sync(0xffffffffu, p, 2);

            float w = __expf(p);
            wsum  += w;
            acc.x += w * cur.x; acc.y += w * cur.y;
            acc.z += w * cur.z; acc.w += w * cur.w;
        }
    }

    float inv = 1.0f / (wsum + 1e-7f);
    float4 b4 = ((const float4*)bias)[lane];
    float v[4] = { acc.x * inv + b4.x, acc.y * inv + b4.y,
                   acc.z * inv + b4.z, acc.w * inv + b4.w };
    #pragma unroll
    for (int j = 0; j < 4; j++) {
        float u = v[j];
        float c = 0.7978845608028654f * (u + 0.044715f * u * u * u);
        v[j] = 0.5f * u * (1.0f + tanhf(c));
    }
    ((float4*)(out + (size_t)t * D))[lane] = make_float4(v[0], v[1], v[2], v[3]);
}

// ---------------- launch: gemm || (hist -> offsets -> (fill || sort-chain)) -> gat ----------------
extern "C" void kernel_launch(void* const* d_in, const int* in_sizes, int n_in,
                              void* d_out, int out_size) {
    const float* x     = (const float*)d_in[0];
    const int*   edges = (const int*)  d_in[1];
    const float* W     = (const float*)d_in[2];
    const float* ka    = (const float*)d_in[3];
    const float* ba    = (const float*)d_in[4];
    const float* bias  = (const float*)d_in[5];
    float* out = (float*)d_out;

    (void)in_sizes; (void)n_in; (void)out_size;

    static cudaStream_t s_gemm = nullptr, s_sort = nullptr;
    static cudaEvent_t  ev_f1 = nullptr, ev_j1 = nullptr, ev_f2 = nullptr, ev_j2 = nullptr;
    if (s_gemm == nullptr) {
        cudaStreamCreateWithFlags(&s_gemm, cudaStreamNonBlocking);
        cudaStreamCreateWithFlags(&s_sort, cudaStreamNonBlocking);
        cudaEventCreateWithFlags(&ev_f1, cudaEventDisableTiming);
        cudaEventCreateWithFlags(&ev_j1, cudaEventDisableTiming);
        cudaEventCreateWithFlags(&ev_f2, cudaEventDisableTiming);
        cudaEventCreateWithFlags(&ev_j2, cudaEventDisableTiming);
    }

    // fork 1: gemm on side stream
    cudaEventRecord(ev_f1, 0);
    cudaStreamWaitEvent(s_gemm, ev_f1, 0);
    gemm_kernel<<<N_NODES / 16, 128, 0, s_gemm>>>(x, W);

    // main: hist -> offsets
    hist_kernel<<<(N_EDGES + 255) / 256, 256>>>(edges);

    // fork 2: degree-sort chain (needs g_deg from hist) parallel to offsets+fill
    cudaEventRecord(ev_f2, 0);
    cudaStreamWaitEvent(s_sort, ev_f2, 0);
    dhist_kernel<<<(N_NODES + 255) / 256, 256, 0, s_sort>>>();
    dscan_kernel<<<1, DBINS, 0, s_sort>>>();
    dorder_kernel<<<(N_NODES + 255) / 256, 256, 0, s_sort>>>();

    offsets_kernel<<<(N_NODES + 255) / 256, 256>>>();
    fill_kernel<<<(N_EDGES + 255) / 256, 256>>>(edges);

    // joins: gat needs gemm, fill, and sort chain
    cudaEventRecord(ev_j1, s_gemm);
    cudaStreamWaitEvent(0, ev_j1, 0);
    cudaEventRecord(ev_j2, s_sort);
    cudaStreamWaitEvent(0, ev_j2, 0);

    gat_kernel<<<(N_NODES + 7) / 8, 256>>>(ka, ba, bias, out);
}

// round 15
// speedup vs baseline: 1.9117x; 1.3747x over previous
#include <cuda_runtime.h>
#include <cuda_fp16.h>
#include <math.h>

#define N_NODES 50000
#define N_EDGES 800000
#define D 128
#define HEADS 8
#define UNITS 16

// ---------------- device scratch (zero-initialized at load) ----------------
__device__ __half g_xph[N_NODES * D];    // 12.8 MB  x @ W in fp16 (fp32 accum, rounded once)
__device__ int    g_deg[N_NODES];        // degree per target (self-cleaning: gat resets)
__device__ int    g_off[N_NODES];        // start of target's region in g_esrc
__device__ int    g_cur[N_NODES];        // bump cursor for fill
__device__ int    g_esrc[N_EDGES];       // sources grouped by target (compact CSR)
__device__ int    g_total;               // bump allocator (reset by hist_kernel)

__device__ __forceinline__ float lrelu(float v) {
    return fmaxf(v, 0.2f * v);
}

__device__ __forceinline__ uint2 pack_half4(float4 v) {
    __half2 a = __floats2half2_rn(v.x, v.y);
    __half2 b = __floats2half2_rn(v.z, v.w);
    uint2 r;
    r.x = *(const unsigned int*)&a;
    r.y = *(const unsigned int*)&b;
    return r;
}

__device__ __forceinline__ float4 unpack_half4(uint2 r) {
    __half2 a = *(const __half2*)&r.x;
    __half2 b = *(const __half2*)&r.y;
    float2 f0 = __half22float2(a);
    float2 f1 = __half22float2(b);
    return make_float4(f0.x, f0.y, f1.x, f1.y);
}

// ---------------- kernel 1: xp = x @ W — fp32 accum, fp16 store ----------------
#define XPAD 20
__global__ void gemm_kernel(const float* __restrict__ x, const float* __restrict__ W) {
    __shared__ float xs_t[D][XPAD];
    int node0 = blockIdx.x * 16;
    int tid = threadIdx.x;
    int cg = tid & 31;
    int ng = tid >> 5;

    #pragma unroll
    for (int m = 0; m < 16; m++)
        xs_t[tid][m] = x[(node0 + m) * D + tid];
    __syncthreads();

    const float4* W4 = (const float4*)W;
    float4 acc0 = make_float4(0.f, 0.f, 0.f, 0.f);
    float4 acc1 = acc0, acc2 = acc0, acc3 = acc0;

    #pragma unroll 8
    for (int k = 0; k < D; k++) {
        float4 w4 = W4[k * 32 + cg];
        float4 xv = *(const float4*)&xs_t[k][4 * ng];
        acc0.x += xv.x * w4.x; acc0.y += xv.x * w4.y; acc0.z += xv.x * w4.z; acc0.w += xv.x * w4.w;
        acc1.x += xv.y * w4.x; acc1.y += xv.y * w4.y; acc1.z += xv.y * w4.z; acc1.w += xv.y * w4.w;
        acc2.x += xv.z * w4.x; acc2.y += xv.z * w4.y; acc2.z += xv.z * w4.z; acc2.w += xv.z * w4.w;
        acc3.x += xv.w * w4.x; acc3.y += xv.w * w4.y; acc3.z += xv.w * w4.z; acc3.w += xv.w * w4.w;
    }

    // fp16 store: 256B per warp per node row, coalesced
    uint2* o0 = (uint2*)(g_xph + (size_t)(node0 + 4 * ng + 0) * D);
    uint2* o1 = (uint2*)(g_xph + (size_t)(node0 + 4 * ng + 1) * D);
    uint2* o2 = (uint2*)(g_xph + (size_t)(node0 + 4 * ng + 2) * D);
    uint2* o3 = (uint2*)(g_xph + (size_t)(node0 + 4 * ng + 3) * D);
    o0[cg] = pack_half4(acc0);
    o1[cg] = pack_half4(acc1);
    o2[cg] = pack_half4(acc2);
    o3[cg] = pack_half4(acc3);
}

// ---------------- kernel 2: degree histogram (R9-exact) ----------------
__global__ void hist_kernel(const int* __restrict__ edges) {
    if (blockIdx.x == 0 && threadIdx.x == 0) g_total = 0;
    int e = blockIdx.x * blockDim.x + threadIdx.x;
    if (e >= N_EDGES) return;
    int tgt = edges[2 * e + 1];
    atomicAdd(&g_deg[tgt], 1);
}

// ---------------- kernel 3: offsets via warp-aggregated bump alloc (R9-exact) ----------------
__global__ void offsets_kernel() {
    int t = blockIdx.x * blockDim.x + threadIdx.x;
    int lane = threadIdx.x & 31;
    int deg = (t < N_NODES) ? g_deg[t] : 0;

    int incl = deg;
    #pragma unroll
    for (int d = 1; d < 32; d <<= 1) {
        int v = __shfl_up_sync(0xffffffffu, incl, d);
        if (lane >= d) incl += v;
    }
    int total = __shfl_sync(0xffffffffu, incl, 31);
    int base = 0;
    if (lane == 31) base = atomicAdd(&g_total, total);
    base = __shfl_sync(0xffffffffu, base, 31);

    if (t < N_NODES) {
        int off = base + incl - deg;
        g_off[t] = off;
        g_cur[t] = off;
    }
}

// ---------------- kernel 4: scatter sources into per-target regions (R9-exact) ----------------
__global__ void fill_kernel(const int* __restrict__ edges) {
    int e = blockIdx.x * blockDim.x + threadIdx.x;
    if (e >= N_EDGES) return;
    int2 ed = ((const int2*)edges)[e];
    int pos = atomicAdd(&g_cur[ed.y], 1);
    g_esrc[pos] = ed.x;
}

// ---------------- kernel 5: fused GAT pass, warp per target (R10 body, fp16 gathers) ----------------
__global__ void gat_kernel(const float* __restrict__ ka,
                           const float* __restrict__ ba,
                           const float* __restrict__ bias,
                           float* __restrict__ out) {
    int t = blockIdx.x * (blockDim.x >> 5) + (threadIdx.x >> 5);
    if (t >= N_NODES) return;
    int lane = threadIdx.x & 31;

    int off = g_off[t];
    int deg = g_deg[t];
    if (lane == 0) g_deg[t] = 0;                 // self-clean for next replay

    float4 k4  = ((const float4*)ka)[lane];
    float4 ba4 = ((const float4*)ba)[lane];
    float4 tb  = unpack_half4(((const uint2*)(g_xph + (size_t)t * D))[lane]);
    tb.x += 2.0f * ba4.x; tb.y += 2.0f * ba4.y;
    tb.z += 2.0f * ba4.z; tb.w += 2.0f * ba4.w;

    float4 acc = make_float4(0.0f, 0.0f, 0.0f, 0.0f);
    float wsum = 0.0f;

    if (deg > 0) {
        int last = deg - 1;
        const int* __restrict__ srcs = g_esrc + off;

        uint2 r0 = ((const uint2*)(g_xph + (size_t)srcs[0] * D))[lane];
        uint2 r1 = ((const uint2*)(g_xph + (size_t)srcs[min(1, last)] * D))[lane];

        for (int i = 0; i < deg; i++) {
            float4 cur = unpack_half4(r0);
            r0 = r1;
            int s = srcs[min(i + 2, last)];
            r1 = ((const uint2*)(g_xph + (size_t)s * D))[lane];

            float p = lrelu(cur.x + tb.x) * k4.x
                    + lrelu(cur.y + tb.y) * k4.y
                    + lrelu(cur.z + tb.z) * k4.z
                    + lrelu(cur.w + tb.w) * k4.w;
            p += __shfl_xor_sync(0xffffffffu, p, 1);
            p += __shfl_xor_sync(0xffffffffu, p, 2);

            float w = __expf(p);
            wsum  += w;
            acc.x += w * cur.x; acc.y += w * cur.y;
            acc.z += w * cur.z; acc.w += w * cur.w;
        }
    }

    float inv = 1.0f / (wsum + 1e-7f);
    float4 b4 = ((const float4*)bias)[lane];
    float v[4] = { acc.x * inv + b4.x, acc.y * inv + b4.y,
                   acc.z * inv + b4.z, acc.w * inv + b4.w };
    #pragma unroll
    for (int j = 0; j < 4; j++) {
        float u = v[j];
        float c = 0.7978845608028654f * (u + 0.044715f * u * u * u);
        v[j] = 0.5f * u * (1.0f + tanhf(c));
    }
    ((float4*)(out + (size_t)t * D))[lane] = make_float4(v[0], v[1], v[2], v[3]);
}

// ---------------- launch: fork gemm onto a side stream, join before gat (R10-exact) ----------------
extern "C" void kernel_launch(void* const* d_in, const int* in_sizes, int n_in,
                              void* d_out, int out_size) {
    const float* x     = (const float*)d_in[0];
    const int*   edges = (const int*)  d_in[1];
    const float* W     = (const float*)d_in[2];
    const float* ka    = (const float*)d_in[3];
    const float* ba    = (const float*)d_in[4];
    const float* bias  = (const float*)d_in[5];
    float* out = (float*)d_out;

    (void)in_sizes; (void)n_in; (void)out_size;

    static cudaStream_t s_side = nullptr;
    static cudaEvent_t  ev_fork = nullptr, ev_join = nullptr;
    if (s_side == nullptr) {
        cudaStreamCreateWithFlags(&s_side, cudaStreamNonBlocking);
        cudaEventCreateWithFlags(&ev_fork, cudaEventDisableTiming);
        cudaEventCreateWithFlags(&ev_join, cudaEventDisableTiming);
    }

    cudaEventRecord(ev_fork, 0);
    cudaStreamWaitEvent(s_side, ev_fork, 0);

    gemm_kernel<<<N_NODES / 16, 128, 0, s_side>>>(x, W);

    hist_kernel<<<(N_EDGES + 255) / 256, 256>>>(edges);
    offsets_kernel<<<(N_NODES + 255) / 256, 256>>>();
    fill_kernel<<<(N_EDGES + 255) / 256, 256>>>(edges);

    cudaEventRecord(ev_join, s_side);
    cudaStreamWaitEvent(0, ev_join, 0);

    gat_kernel<<<(N_NODES + 7) / 8, 256>>>(ka, ba, bias, out);
}